// round 10
// baseline (speedup 1.0000x reference)
#include <cuda_runtime.h>
#include <cuda_bf16.h>
#include <math.h>
#include <stdint.h>

// Problem constants
#define B_  4
#define L_  2048
#define C_  2048
#define NH_ 32
#define HD_ 64
#define K_  16
#define NC_ 128
#define EPS_ 1e-6f
#define M_  8192          // B_*L_

// ---------------------------------------------------------------------------
// Device-global scratch
// ---------------------------------------------------------------------------
__device__ __nv_bfloat16 g_Ah[(size_t)M_ * C_];        // hs hi
__device__ __nv_bfloat16 g_Al[(size_t)M_ * C_];        // hs lo
__device__ __nv_bfloat16 g_Wh[(size_t)4 * C_ * C_];    // Wq,Wk,Wv,Wo transposed [N][K] hi
__device__ __nv_bfloat16 g_Wl[(size_t)4 * C_ * C_];    // lo
__device__ __nv_bfloat16 g_XCWh[(size_t)M_ * C_];      // scan output hi
__device__ __nv_bfloat16 g_XCWl[(size_t)M_ * C_];      // scan output lo
__device__ float g_XC[(size_t)B_ * NH_ * L_ * HD_];    // [b][h][l][d]
__device__ float g_XB[(size_t)B_ * NH_ * L_ * HD_];
__device__ float g_XA[(size_t)B_ * NH_ * L_ * HD_];
__device__ float g_coeff[(size_t)B_ * NH_ * L_];

// ---------------------------------------------------------------------------
// Helpers
// ---------------------------------------------------------------------------
__device__ __forceinline__ uint32_t smem_u32(const void* p) {
    uint32_t a;
    asm("{ .reg .u64 t; cvta.to.shared.u64 t, %1; cvt.u32.u64 %0, t; }"
        : "=r"(a) : "l"(p));
    return a;
}

#define CP_ASYNC16(smaddr, gptr) \
    asm volatile("cp.async.cg.shared.global [%0], [%1], 16;" \
                 :: "r"(smaddr), "l"(gptr))
#define CP_COMMIT() asm volatile("cp.async.commit_group;")
#define CP_WAIT0()  asm volatile("cp.async.wait_group 0;")
#define CP_WAIT1()  asm volatile("cp.async.wait_group 1;")

#define LDSM_X4(r0, r1, r2, r3, addr) \
    asm volatile("ldmatrix.sync.aligned.m8n8.x4.shared.b16 {%0,%1,%2,%3}, [%4];" \
                 : "=r"(r0), "=r"(r1), "=r"(r2), "=r"(r3) : "r"(addr))

__device__ __forceinline__ void mma_bf16(float* c, const uint32_t* a,
                                         uint32_t b0, uint32_t b1) {
    asm volatile(
        "mma.sync.aligned.m16n8k16.row.col.f32.bf16.bf16.f32 "
        "{%0,%1,%2,%3}, {%4,%5,%6,%7}, {%8,%9}, {%0,%1,%2,%3};"
        : "+f"(c[0]), "+f"(c[1]), "+f"(c[2]), "+f"(c[3])
        : "r"(a[0]), "r"(a[1]), "r"(a[2]), "r"(a[3]), "r"(b0), "r"(b1));
}

// ---------------------------------------------------------------------------
// Fused prep kernel: conv hs->hi/lo (blocks [0,16384)), weight transpose+split
// (blocks [16384,32768)), ilr/coeff (blocks [32768,33792)). 256 threads.
// ---------------------------------------------------------------------------
#define NCONV 16384
#define NWT   16384
#define NILR  1024
#define PREP_SMEM 32768

__global__ __launch_bounds__(256) void prep_kernel(
    const float* __restrict__ hs,
    const float* __restrict__ Wq, const float* __restrict__ Wk,
    const float* __restrict__ Wv, const float* __restrict__ Wo,
    const float* __restrict__ ilr_w, const float* __restrict__ ilr_b)
{
    extern __shared__ char psm[];
    int bid = blockIdx.x;
    int tid = threadIdx.x;

    if (bid < NCONV) {
        size_t i = ((size_t)bid * 256 + tid) * 4;
        float4 v = *(const float4*)(hs + i);
        __nv_bfloat16 h0 = __float2bfloat16(v.x), h1 = __float2bfloat16(v.y);
        __nv_bfloat16 h2 = __float2bfloat16(v.z), h3 = __float2bfloat16(v.w);
        g_Ah[i] = h0; g_Ah[i+1] = h1; g_Ah[i+2] = h2; g_Ah[i+3] = h3;
        g_Al[i]   = __float2bfloat16(v.x - __bfloat162float(h0));
        g_Al[i+1] = __float2bfloat16(v.y - __bfloat162float(h1));
        g_Al[i+2] = __float2bfloat16(v.z - __bfloat162float(h2));
        g_Al[i+3] = __float2bfloat16(v.w - __bfloat162float(h3));
    } else if (bid < NCONV + NWT) {
        float (*t)[33] = (float(*)[33])psm;
        int id = bid - NCONV;
        int z = id >> 12;
        int rem = id & 4095;
        const float* W = (z == 0) ? Wq : (z == 1) ? Wk : (z == 2) ? Wv : Wo;
        __nv_bfloat16* Oh = g_Wh + (size_t)z * (C_ * C_);
        __nv_bfloat16* Ol = g_Wl + (size_t)z * (C_ * C_);
        int n0 = (rem & 63) * 32, k0 = (rem >> 6) * 32;
        int tx = tid & 31, ty = tid >> 5;
        #pragma unroll
        for (int i = 0; i < 4; ++i)
            t[ty + 8 * i][tx] = W[(size_t)(k0 + ty + 8 * i) * C_ + n0 + tx];
        __syncthreads();
        #pragma unroll
        for (int i = 0; i < 4; ++i) {
            float v = t[tx][ty + 8 * i];
            __nv_bfloat16 hv = __float2bfloat16(v);
            size_t o = (size_t)(n0 + ty + 8 * i) * C_ + k0 + tx;
            Oh[o] = hv;
            Ol[o] = __float2bfloat16(v - __bfloat162float(hv));
        }
    } else {
        float* wsm = (float*)psm;
        int id = bid - NCONV - NWT;
        int h = tid & 31, mr = tid >> 5;            // 8 rows/block
        int m = id * 8 + mr;
        const float* row = hs + (size_t)m * C_;
        float acc = 0.f;
        for (int kt = 0; kt < 8; ++kt) {
            for (int i = tid; i < 256 * 32; i += 256)
                wsm[i] = ilr_w[(size_t)kt * 256 * 32 + i];
            __syncthreads();
            #pragma unroll 4
            for (int k = 0; k < 256; ++k)
                acc = fmaf(row[kt * 256 + k], wsm[k * 32 + h], acc);
            __syncthreads();
        }
        acc += ilr_b[h];
        float sig = 1.f / (1.f + expf(-acc));
        int b = m >> 11, l = m & 2047;
        g_coeff[((size_t)(b * NH_ + h)) * L_ + l] =
            sig * (1.0f / (float)HD_) / (float)((l & 15) + 1);
    }
}

// ---------------------------------------------------------------------------
// mma.sync GEMM: 128x128 tile, BK=32, 256 threads (8 warps, 64x32 warp tile),
// 3-stage cp.async pipeline with ONE __syncthreads per chunk.
// Per-accumulator FP order identical to R4/R7/R8 -> rel_err invariant.
// ---------------------------------------------------------------------------
#define ROWB 80
#define MATB (128 * ROWB)          // 10240
#define STGB (4 * MATB)            // 40960
#define GEMM_SMEM (3 * STGB)       // 122880

__device__ __forceinline__ void load_stage(uint32_t sb,
    const __nv_bfloat16* __restrict__ Ah, const __nv_bfloat16* __restrict__ Al,
    const __nv_bfloat16* __restrict__ Bh, const __nv_bfloat16* __restrict__ Bl,
    int am0, int bn0, int kc, int tid)
{
    #pragma unroll
    for (int it = 0; it < 2; ++it) {
        int u = tid + it * 256;
        int row = u >> 2, ch = u & 3;
        int gcol = kc * 32 + ch * 8;
        uint32_t so = (uint32_t)(row * ROWB + ch * 16);
        size_t ga = (size_t)(am0 + row) * C_ + gcol;
        size_t gb = (size_t)(bn0 + row) * C_ + gcol;
        CP_ASYNC16(sb + so,            Ah + ga);
        CP_ASYNC16(sb + so + MATB,     Al + ga);
        CP_ASYNC16(sb + so + 2 * MATB, Bh + gb);
        CP_ASYNC16(sb + so + 3 * MATB, Bl + gb);
    }
}

template <int MODE>
__global__ __launch_bounds__(256) void gemm_mma(float* __restrict__ Cout)
{
    extern __shared__ char sm[];
    uint32_t sbase = smem_u32(sm);
    int tid = threadIdx.x, wid = tid >> 5, lane = tid & 31;
    int bn = blockIdx.x, bm = blockIdx.y;
    int wm = wid & 1, wn = wid >> 1;     // warp 64x32 tile: 2 x 4 warps

    const __nv_bfloat16 *Ah, *Al, *Bh, *Bl;
    float* outP;
    if (MODE == 1) {
        int z = blockIdx.z;
        Ah = g_Ah; Al = g_Al;
        Bh = g_Wh + (size_t)z * (C_ * C_);
        Bl = g_Wl + (size_t)z * (C_ * C_);
        outP = (z == 0) ? g_XC : (z == 1) ? g_XB : g_XA;
    } else {
        Ah = g_XCWh; Al = g_XCWl;
        Bh = g_Wh + (size_t)3 * (C_ * C_);
        Bl = g_Wl + (size_t)3 * (C_ * C_);
        outP = Cout;
    }
    int am0 = bm * 128, bn0 = bn * 128;

    float acc[4][4][4];
    #pragma unroll
    for (int i = 0; i < 4; ++i)
        #pragma unroll
        for (int j = 0; j < 4; ++j)
            #pragma unroll
            for (int q = 0; q < 4; ++q) acc[i][j][q] = 0.f;

    int a_row = wm * 64 + (lane & 15);
    int a_cb  = (lane >> 4) * 16;
    int g = lane >> 3, l8 = lane & 7;
    int b_row = wn * 32 + (g >> 1) * 8 + l8;
    int b_cb  = (g & 1) * 16;

    uint32_t stg[3] = {sbase, sbase + STGB, sbase + 2 * STGB};

    load_stage(stg[0], Ah, Al, Bh, Bl, am0, bn0, 0, tid);
    CP_COMMIT();
    load_stage(stg[1], Ah, Al, Bh, Bl, am0, bn0, 1, tid);
    CP_COMMIT();

    for (int c = 0; c < 64; ++c) {
        if (c < 63) { CP_WAIT1(); } else { CP_WAIT0(); }
        __syncthreads();
        if (c + 2 < 64) {
            load_stage(stg[(c + 2) % 3], Ah, Al, Bh, Bl, am0, bn0, c + 2, tid);
            CP_COMMIT();
        }

        uint32_t S = stg[c % 3];
        #pragma unroll
        for (int k16 = 0; k16 < 2; ++k16) {
            uint32_t kb = (uint32_t)(k16 * 32);
            uint32_t bh[8], bl[8];
            {
                uint32_t ad0 = S + 2 * MATB + (uint32_t)((b_row) * ROWB) + kb + b_cb;
                uint32_t ad1 = ad0 + 16 * ROWB;
                LDSM_X4(bh[0], bh[1], bh[2], bh[3], ad0);
                LDSM_X4(bh[4], bh[5], bh[6], bh[7], ad1);
                LDSM_X4(bl[0], bl[1], bl[2], bl[3], ad0 + MATB);
                LDSM_X4(bl[4], bl[5], bl[6], bl[7], ad1 + MATB);
            }
            #pragma unroll
            for (int mt = 0; mt < 4; ++mt) {
                uint32_t ah[4], al[4];
                uint32_t aad = S + (uint32_t)((a_row + mt * 16) * ROWB) + kb + a_cb;
                LDSM_X4(ah[0], ah[1], ah[2], ah[3], aad);
                LDSM_X4(al[0], al[1], al[2], al[3], aad + MATB);
                #pragma unroll
                for (int nt = 0; nt < 4; ++nt)
                    mma_bf16(acc[mt][nt], ah, bh[nt * 2], bh[nt * 2 + 1]);
                #pragma unroll
                for (int nt = 0; nt < 4; ++nt)
                    mma_bf16(acc[mt][nt], ah, bl[nt * 2], bl[nt * 2 + 1]);
                #pragma unroll
                for (int nt = 0; nt < 4; ++nt)
                    mma_bf16(acc[mt][nt], al, bh[nt * 2], bh[nt * 2 + 1]);
            }
        }
    }

    __syncthreads();

    #pragma unroll
    for (int mt = 0; mt < 4; ++mt) {
        #pragma unroll
        for (int nt = 0; nt < 4; ++nt) {
            int m = am0 + wm * 64 + mt * 16 + (lane >> 2);
            int n = bn0 + wn * 32 + nt * 8 + 2 * (lane & 3);
            float2 v0 = make_float2(acc[mt][nt][0], acc[mt][nt][1]);
            float2 v1 = make_float2(acc[mt][nt][2], acc[mt][nt][3]);
            if (MODE == 0) {
                *(float2*)(outP + (size_t)m * C_ + n) = v0;
                *(float2*)(outP + (size_t)(m + 8) * C_ + n) = v1;
            } else {
                int h = n >> 6, d = n & 63;
                int b = m >> 11, l = m & 2047;
                float* dst = outP + ((size_t)(b * NH_ + h) * L_ + l) * HD_ + d;
                *(float2*)dst = v0;
                *(float2*)(dst + 8 * HD_) = v1;
            }
        }
    }
}

// ---------------------------------------------------------------------------
// Scan kernel: per-chunk matmuls on tensor cores (3-pass bf16 hi/lo).
// W1 master fp32 stored TRANSPOSED [d][k]; non-trans ldmatrix recipes only.
// ---------------------------------------------------------------------------
#define SC_W1T    0                       // fp32 [64][66]
#define SC_W1TH   16896                   // bf16 [64] pitch 144
#define SC_W1TL   26112
#define SC_XBH    35328                   // bf16 [16] pitch 144
#define SC_XBL    37632
#define SC_XCH    39936
#define SC_XCL    42240
#define SC_XBT_H  44544                   // xb^T bf16 [64] pitch 48
#define SC_XBT_L  47616
#define SC_GT_H   50688                   // grad^T bf16 [64] pitch 48
#define SC_GT_L   53760
#define SC_Z1S    56832                   // fp32 [16][66]
#define SC_ACCS   61056                   // fp32 [16][66]
#define SC_XBS    65280                   // fp32 [16][65]
#define SC_XCS    69440
#define SC_GRADS  73600
#define SC_ATTN   77760                   // fp32 [16][16]
#define SC_B1     78784
#define SC_COS    79040
#define SC_RED    79104
#define SC_TOTAL  79360

__device__ __forceinline__ void reduce2s(float& a, float& b, float* red, int tid)
{
    #pragma unroll
    for (int off = 16; off; off >>= 1) {
        a += __shfl_xor_sync(0xffffffffu, a, off);
        b += __shfl_xor_sync(0xffffffffu, b, off);
    }
    int warp = tid >> 5;
    __syncthreads();
    if ((tid & 31) == 0) { red[warp * 2] = a; red[warp * 2 + 1] = b; }
    __syncthreads();
    int rr = tid >> 6;
    a = red[rr * 4 + 0] + red[rr * 4 + 2];
    b = red[rr * 4 + 1] + red[rr * 4 + 3];
}

__global__ __launch_bounds__(1024) void scan_kernel(const float* __restrict__ W1g,
                                                    const float* __restrict__ b1g,
                                                    const float* __restrict__ lnwg,
                                                    const float* __restrict__ lnbg)
{
    extern __shared__ char sm[];
    uint32_t sbase = smem_u32(sm);
    float* W1Tp  = (float*)(sm + SC_W1T);
    float* z1s   = (float*)(sm + SC_Z1S);
    float* accs  = (float*)(sm + SC_ACCS);
    float* xbs   = (float*)(sm + SC_XBS);
    float* xcs   = (float*)(sm + SC_XCS);
    float* grads = (float*)(sm + SC_GRADS);
    float* attn  = (float*)(sm + SC_ATTN);
    float* b1s   = (float*)(sm + SC_B1);
    float* cosp  = (float*)(sm + SC_COS);
    float* red   = (float*)(sm + SC_RED);

    int bh = blockIdx.x;
    int h = bh & 31;
    int b = bh >> 5;
    int tid = threadIdx.x;
    int wid = tid >> 5, lane = tid & 31;
    int r = tid >> 6;
    int d = tid & 63;

    for (int i = tid; i < 4096; i += 1024) {
        int dd = i & 63, kk = i >> 6;
        float v = W1g[(size_t)h * 4096 + kk * 64 + dd];
        W1Tp[dd * 66 + kk] = v;
        __nv_bfloat16 hv = __float2bfloat16(v);
        *(__nv_bfloat16*)(sm + SC_W1TH + dd * 144 + kk * 2) = hv;
        *(__nv_bfloat16*)(sm + SC_W1TL + dd * 144 + kk * 2) =
            __float2bfloat16(v - __bfloat162float(hv));
    }
    if (tid < 64) b1s[tid] = b1g[(size_t)h * 64 + tid];
    float lnw = lnwg[(size_t)h * 64 + d];
    float lnb = lnbg[(size_t)h * 64 + d];

    const float* XCp = g_XC + (size_t)bh * (L_ * HD_);
    const float* XBp = g_XB + (size_t)bh * (L_ * HD_);
    const float* XAp = g_XA + (size_t)bh * (L_ * HD_);
    const float* cop = g_coeff + (size_t)bh * L_;

    __syncthreads();

    for (int c = 0; c < NC_; ++c) {
        int base = c * (K_ * HD_) + tid;
        float xb_e = XBp[base];
        float xc_e = XCp[base];
        float xa_e = XAp[base];
        xbs[r * 65 + d] = xb_e;
        xcs[r * 65 + d] = xc_e;
        {
            __nv_bfloat16 bh16 = __float2bfloat16(xb_e);
            __nv_bfloat16 bl16 = __float2bfloat16(xb_e - __bfloat162float(bh16));
            *(__nv_bfloat16*)(sm + SC_XBH + r * 144 + d * 2) = bh16;
            *(__nv_bfloat16*)(sm + SC_XBL + r * 144 + d * 2) = bl16;
            *(__nv_bfloat16*)(sm + SC_XBT_H + d * 48 + r * 2) = bh16;
            *(__nv_bfloat16*)(sm + SC_XBT_L + d * 48 + r * 2) = bl16;
            __nv_bfloat16 ch16 = __float2bfloat16(xc_e);
            *(__nv_bfloat16*)(sm + SC_XCH + r * 144 + d * 2) = ch16;
            *(__nv_bfloat16*)(sm + SC_XCL + r * 144 + d * 2) =
                __float2bfloat16(xc_e - __bfloat162float(ch16));
        }
        if (tid < 16) cosp[tid] = cop[c * 16 + tid];
        __syncthreads();

        if (wid < 8) {
            int isAcc = wid >> 2;
            int w = wid & 3;
            uint32_t AhB = sbase + (isAcc ? SC_XCH : SC_XBH);
            uint32_t AlB = sbase + (isAcc ? SC_XCL : SC_XBL);
            int n0 = w * 16;
            float c0[4] = {0,0,0,0}, c1[4] = {0,0,0,0};
            uint32_t a_off = (uint32_t)((lane & 15) * 144 + (lane >> 4) * 16);
            int g = lane >> 3;
            uint32_t b_off = (uint32_t)((n0 + ((g >> 1) << 3) + (lane & 7)) * 144 + (g & 1) * 16);
            #pragma unroll
            for (int ks = 0; ks < 4; ++ks) {
                uint32_t ah[4], al[4], bhf[4], blf[4];
                LDSM_X4(ah[0], ah[1], ah[2], ah[3], AhB + a_off + ks * 32);
                LDSM_X4(al[0], al[1], al[2], al[3], AlB + a_off + ks * 32);
                LDSM_X4(bhf[0], bhf[1], bhf[2], bhf[3], sbase + SC_W1TH + b_off + ks * 32);
                LDSM_X4(blf[0], blf[1], blf[2], blf[3], sbase + SC_W1TL + b_off + ks * 32);
                mma_bf16(c0, ah, bhf[0], bhf[1]); mma_bf16(c1, ah, bhf[2], bhf[3]);
                mma_bf16(c0, ah, blf[0], blf[1]); mma_bf16(c1, ah, blf[2], blf[3]);
                mma_bf16(c0, al, bhf[0], bhf[1]); mma_bf16(c1, al, bhf[2], bhf[3]);
            }
            float* outb = isAcc ? accs : z1s;
            int row = lane >> 2, col0 = n0 + 2 * (lane & 3);
            *(float2*)&outb[row * 66 + col0]           = make_float2(c0[0], c0[1]);
            *(float2*)&outb[(row + 8) * 66 + col0]     = make_float2(c0[2], c0[3]);
            *(float2*)&outb[row * 66 + col0 + 8]       = make_float2(c1[0], c1[1]);
            *(float2*)&outb[(row + 8) * 66 + col0 + 8] = make_float2(c1[2], c1[3]);
        } else if (wid == 8) {
            float c0[4] = {0,0,0,0}, c1[4] = {0,0,0,0};
            uint32_t a_off = (uint32_t)((lane & 15) * 144 + (lane >> 4) * 16);
            int g = lane >> 3;
            uint32_t b_off = (uint32_t)((((g >> 1) << 3) + (lane & 7)) * 144 + (g & 1) * 16);
            #pragma unroll
            for (int ks = 0; ks < 4; ++ks) {
                uint32_t ah[4], al[4], bhf[4], blf[4];
                LDSM_X4(ah[0], ah[1], ah[2], ah[3], sbase + SC_XCH + a_off + ks * 32);
                LDSM_X4(al[0], al[1], al[2], al[3], sbase + SC_XCL + a_off + ks * 32);
                LDSM_X4(bhf[0], bhf[1], bhf[2], bhf[3], sbase + SC_XBH + b_off + ks * 32);
                LDSM_X4(blf[0], blf[1], blf[2], blf[3], sbase + SC_XBL + b_off + ks * 32);
                mma_bf16(c0, ah, bhf[0], bhf[1]); mma_bf16(c1, ah, bhf[2], bhf[3]);
                mma_bf16(c0, ah, blf[0], blf[1]); mma_bf16(c1, ah, blf[2], blf[3]);
                mma_bf16(c0, al, bhf[0], bhf[1]); mma_bf16(c1, al, bhf[2], bhf[3]);
            }
            int row = lane >> 2, col0 = 2 * (lane & 3);
            *(float2*)&attn[row * 16 + col0]           = make_float2(c0[0], c0[1]);
            *(float2*)&attn[(row + 8) * 16 + col0]     = make_float2(c0[2], c0[3]);
            *(float2*)&attn[row * 16 + col0 + 8]       = make_float2(c1[0], c1[1]);
            *(float2*)&attn[(row + 8) * 16 + col0 + 8] = make_float2(c1[2], c1[3]);
        }
        __syncthreads();

        float z1 = z1s[r * 66 + d] + b1s[d];
        float s1 = z1, s2 = z1 * z1;
        reduce2s(s1, s2, red, tid);
        float mu = s1 * (1.f / 64.f);
        float var = s2 * (1.f / 64.f) - mu * mu;
        float rstd = rsqrtf(var + EPS_);
        float xhat = (z1 - mu) * rstd;
        float y = fmaf(lnw, xhat, lnb);
        float g = (y - (xa_e - xb_e)) * lnw;
        float sg = g, sgx = g * xhat;
        reduce2s(sg, sgx, red, tid);
        float grad = (64.f * g - sg - xhat * sgx) * (rstd * (1.f / 64.f));
        grads[r * 65 + d] = grad;
        {
            __nv_bfloat16 gh = __float2bfloat16(grad);
            *(__nv_bfloat16*)(sm + SC_GT_H + d * 48 + r * 2) = gh;
            *(__nv_bfloat16*)(sm + SC_GT_L + d * 48 + r * 2) =
                __float2bfloat16(grad - __bfloat162float(gh));
        }
        __syncthreads();

        if (wid >= 8 && wid < 16) {
            int wq = wid - 8;
            int m0 = (wq >> 1) * 16;
            int nb = (wq & 1) * 32;
            uint32_t a_off = (uint32_t)((m0 + (lane & 15)) * 48 + (lane >> 4) * 16);
            uint32_t ah[4], al[4];
            LDSM_X4(ah[0], ah[1], ah[2], ah[3], sbase + SC_GT_H + a_off);
            LDSM_X4(al[0], al[1], al[2], al[3], sbase + SC_GT_L + a_off);
            int g2 = lane >> 3;
            float cc[4][4];
            #pragma unroll
            for (int i = 0; i < 4; ++i)
                #pragma unroll
                for (int q = 0; q < 4; ++q) cc[i][q] = 0.f;
            #pragma unroll
            for (int half = 0; half < 2; ++half) {
                int n0 = nb + half * 16;
                uint32_t b_off = (uint32_t)((n0 + ((g2 >> 1) << 3) + (lane & 7)) * 48 + (g2 & 1) * 16);
                uint32_t bhf[4], blf[4];
                LDSM_X4(bhf[0], bhf[1], bhf[2], bhf[3], sbase + SC_XBT_H + b_off);
                LDSM_X4(blf[0], blf[1], blf[2], blf[3], sbase + SC_XBT_L + b_off);
                mma_bf16(cc[half*2],   ah, bhf[0], bhf[1]);
                mma_bf16(cc[half*2+1], ah, bhf[2], bhf[3]);
                mma_bf16(cc[half*2],   ah, blf[0], blf[1]);
                mma_bf16(cc[half*2+1], ah, blf[2], blf[3]);
                mma_bf16(cc[half*2],   al, bhf[0], bhf[1]);
                mma_bf16(cc[half*2+1], al, bhf[2], bhf[3]);
            }
            float c15 = cosp[15];
            int row = m0 + (lane >> 2), colb = 2 * (lane & 3);
            #pragma unroll
            for (int nt = 0; nt < 4; ++nt) {
                int col = nb + nt * 8 + colb;
                float2 v = *(float2*)&W1Tp[row * 66 + col];
                v.x -= c15 * cc[nt][0]; v.y -= c15 * cc[nt][1];
                *(float2*)&W1Tp[row * 66 + col] = v;
                float2 w2 = *(float2*)&W1Tp[(row + 8) * 66 + col];
                w2.x -= c15 * cc[nt][2]; w2.y -= c15 * cc[nt][3];
                *(float2*)&W1Tp[(row + 8) * 66 + col] = w2;
            }
        }
        __syncthreads();

        float acc = accs[r * 66 + d] + b1s[d];
        float s_attn = 0.f, s_cum = 0.f;
        #pragma unroll
        for (int j = 0; j < 16; ++j) {
            float gj = grads[j * 65 + d];
            if (j <= r) {
                s_cum += gj;
                s_attn = fmaf(attn[r * 16 + j], gj, s_attn);
            }
        }
        float co = cosp[r];
        float z1b = acc - co * (s_attn + s_cum);
        float b1new = 0.f;
        if (r == 15) b1new = b1s[d] - co * s_cum;

        float t1 = z1b, t2 = z1b * z1b;
        reduce2s(t1, t2, red, tid);
        float mu2 = t1 * (1.f / 64.f);
        float rstd2 = rsqrtf(t2 * (1.f / 64.f) - mu2 * mu2 + EPS_);
        float outv = xc_e + fmaf(lnw, (z1b - mu2) * rstd2, lnb);
        int l = c * 16 + r;
        size_t oidx = ((size_t)(b * L_ + l)) * C_ + h * 64 + d;
        __nv_bfloat16 hv = __float2bfloat16(outv);
        g_XCWh[oidx] = hv;
        g_XCWl[oidx] = __float2bfloat16(outv - __bfloat162float(hv));

        __syncthreads();
        if (r == 15) b1s[d] = b1new;

        {
            int e = tid * 4;
            int dd = e >> 6, kk = e & 63;
            float2 v0 = *(float2*)&W1Tp[dd * 66 + kk];
            float2 v1 = *(float2*)&W1Tp[dd * 66 + kk + 2];
            __nv_bfloat16* Hh = (__nv_bfloat16*)(sm + SC_W1TH + dd * 144 + kk * 2);
            __nv_bfloat16* Hl = (__nv_bfloat16*)(sm + SC_W1TL + dd * 144 + kk * 2);
            __nv_bfloat16 h0 = __float2bfloat16(v0.x), h1 = __float2bfloat16(v0.y);
            __nv_bfloat16 h2 = __float2bfloat16(v1.x), h3 = __float2bfloat16(v1.y);
            Hh[0] = h0; Hh[1] = h1; Hh[2] = h2; Hh[3] = h3;
            Hl[0] = __float2bfloat16(v0.x - __bfloat162float(h0));
            Hl[1] = __float2bfloat16(v0.y - __bfloat162float(h1));
            Hl[2] = __float2bfloat16(v1.x - __bfloat162float(h2));
            Hl[3] = __float2bfloat16(v1.y - __bfloat162float(h3));
        }
        __syncthreads();
    }
}

// ---------------------------------------------------------------------------
extern "C" void kernel_launch(void* const* d_in, const int* in_sizes, int n_in,
                              void* d_out, int out_size)
{
    const float* hs    = (const float*)d_in[0];
    const float* Wq    = (const float*)d_in[1];
    const float* Wk    = (const float*)d_in[2];
    const float* Wv    = (const float*)d_in[3];
    const float* Wo    = (const float*)d_in[4];
    const float* ilr_w = (const float*)d_in[5];
    const float* ilr_b = (const float*)d_in[6];
    const float* lnw   = (const float*)d_in[7];
    const float* lnb   = (const float*)d_in[8];
    const float* W1    = (const float*)d_in[9];
    const float* b1    = (const float*)d_in[10];
    float* out = (float*)d_out;

    cudaFuncSetAttribute(gemm_mma<1>, cudaFuncAttributeMaxDynamicSharedMemorySize, GEMM_SMEM);
    cudaFuncSetAttribute(gemm_mma<0>, cudaFuncAttributeMaxDynamicSharedMemorySize, GEMM_SMEM);
    cudaFuncSetAttribute(scan_kernel, cudaFuncAttributeMaxDynamicSharedMemorySize, SC_TOTAL);

    prep_kernel<<<NCONV + NWT + NILR, 256, PREP_SMEM>>>(hs, Wq, Wk, Wv, Wo, ilr_w, ilr_b);

    gemm_mma<1><<<dim3(C_ / 128, M_ / 128, 3), 256, GEMM_SMEM>>>(nullptr);

    scan_kernel<<<B_ * NH_, 1024, SC_TOTAL>>>(W1, b1, lnw, lnb);

    gemm_mma<0><<<dim3(C_ / 128, M_ / 128, 1), 256, GEMM_SMEM>>>(out);
}

// round 12
// speedup vs baseline: 1.2374x; 1.2374x over previous
#include <cuda_runtime.h>
#include <cuda_bf16.h>
#include <math.h>
#include <stdint.h>

// Problem constants
#define B_  4
#define L_  2048
#define C_  2048
#define NH_ 32
#define HD_ 64
#define K_  16
#define NC_ 128
#define EPS_ 1e-6f
#define M_  8192          // B_*L_

// ---------------------------------------------------------------------------
// Device-global scratch
// ---------------------------------------------------------------------------
__device__ __nv_bfloat16 g_Ah[(size_t)M_ * C_];        // hs hi
__device__ __nv_bfloat16 g_Al[(size_t)M_ * C_];        // hs lo
__device__ __nv_bfloat16 g_Wh[(size_t)4 * C_ * C_];    // Wq,Wk,Wv,Wo transposed [N][K] hi
__device__ __nv_bfloat16 g_Wl[(size_t)4 * C_ * C_];    // lo
__device__ __nv_bfloat16 g_XCWh[(size_t)M_ * C_];      // scan output hi
__device__ __nv_bfloat16 g_XCWl[(size_t)M_ * C_];      // scan output lo
__device__ float g_XC[(size_t)B_ * NH_ * L_ * HD_];    // [b][h][l][d]
__device__ float g_XB[(size_t)B_ * NH_ * L_ * HD_];
__device__ float g_XA[(size_t)B_ * NH_ * L_ * HD_];
__device__ float g_coeff[(size_t)B_ * NH_ * L_];

// ---------------------------------------------------------------------------
// Helpers
// ---------------------------------------------------------------------------
__device__ __forceinline__ uint32_t smem_u32(const void* p) {
    uint32_t a;
    asm("{ .reg .u64 t; cvta.to.shared.u64 t, %1; cvt.u32.u64 %0, t; }"
        : "=r"(a) : "l"(p));
    return a;
}

#define CP_ASYNC16(smaddr, gptr) \
    asm volatile("cp.async.cg.shared.global [%0], [%1], 16;" \
                 :: "r"(smaddr), "l"(gptr))
#define CP_COMMIT() asm volatile("cp.async.commit_group;")
#define CP_WAIT0()  asm volatile("cp.async.wait_group 0;")
#define CP_WAIT1()  asm volatile("cp.async.wait_group 1;")

#define LDSM_X4(r0, r1, r2, r3, addr) \
    asm volatile("ldmatrix.sync.aligned.m8n8.x4.shared.b16 {%0,%1,%2,%3}, [%4];" \
                 : "=r"(r0), "=r"(r1), "=r"(r2), "=r"(r3) : "r"(addr))

__device__ __forceinline__ void mma_bf16(float* c, const uint32_t* a,
                                         uint32_t b0, uint32_t b1) {
    asm volatile(
        "mma.sync.aligned.m16n8k16.row.col.f32.bf16.bf16.f32 "
        "{%0,%1,%2,%3}, {%4,%5,%6,%7}, {%8,%9}, {%0,%1,%2,%3};"
        : "+f"(c[0]), "+f"(c[1]), "+f"(c[2]), "+f"(c[3])
        : "r"(a[0]), "r"(a[1]), "r"(a[2]), "r"(a[3]), "r"(b0), "r"(b1));
}

// ---------------------------------------------------------------------------
// Fused prep kernel (validated in R10): conv hs, weight transpose, ilr/coeff
// ---------------------------------------------------------------------------
#define NCONV 16384
#define NWT   16384
#define NILR  1024
#define PREP_SMEM 32768

__global__ __launch_bounds__(256) void prep_kernel(
    const float* __restrict__ hs,
    const float* __restrict__ Wq, const float* __restrict__ Wk,
    const float* __restrict__ Wv, const float* __restrict__ Wo,
    const float* __restrict__ ilr_w, const float* __restrict__ ilr_b)
{
    extern __shared__ char psm[];
    int bid = blockIdx.x;
    int tid = threadIdx.x;

    if (bid < NCONV) {
        size_t i = ((size_t)bid * 256 + tid) * 4;
        float4 v = *(const float4*)(hs + i);
        __nv_bfloat16 h0 = __float2bfloat16(v.x), h1 = __float2bfloat16(v.y);
        __nv_bfloat16 h2 = __float2bfloat16(v.z), h3 = __float2bfloat16(v.w);
        g_Ah[i] = h0; g_Ah[i+1] = h1; g_Ah[i+2] = h2; g_Ah[i+3] = h3;
        g_Al[i]   = __float2bfloat16(v.x - __bfloat162float(h0));
        g_Al[i+1] = __float2bfloat16(v.y - __bfloat162float(h1));
        g_Al[i+2] = __float2bfloat16(v.z - __bfloat162float(h2));
        g_Al[i+3] = __float2bfloat16(v.w - __bfloat162float(h3));
    } else if (bid < NCONV + NWT) {
        float (*t)[33] = (float(*)[33])psm;
        int id = bid - NCONV;
        int z = id >> 12;
        int rem = id & 4095;
        const float* W = (z == 0) ? Wq : (z == 1) ? Wk : (z == 2) ? Wv : Wo;
        __nv_bfloat16* Oh = g_Wh + (size_t)z * (C_ * C_);
        __nv_bfloat16* Ol = g_Wl + (size_t)z * (C_ * C_);
        int n0 = (rem & 63) * 32, k0 = (rem >> 6) * 32;
        int tx = tid & 31, ty = tid >> 5;
        #pragma unroll
        for (int i = 0; i < 4; ++i)
            t[ty + 8 * i][tx] = W[(size_t)(k0 + ty + 8 * i) * C_ + n0 + tx];
        __syncthreads();
        #pragma unroll
        for (int i = 0; i < 4; ++i) {
            float v = t[tx][ty + 8 * i];
            __nv_bfloat16 hv = __float2bfloat16(v);
            size_t o = (size_t)(n0 + ty + 8 * i) * C_ + k0 + tx;
            Oh[o] = hv;
            Ol[o] = __float2bfloat16(v - __bfloat162float(hv));
        }
    } else {
        float* wsm = (float*)psm;
        int id = bid - NCONV - NWT;
        int h = tid & 31, mr = tid >> 5;            // 8 rows/block
        int m = id * 8 + mr;
        const float* row = hs + (size_t)m * C_;
        float acc = 0.f;
        for (int kt = 0; kt < 8; ++kt) {
            for (int i = tid; i < 256 * 32; i += 256)
                wsm[i] = ilr_w[(size_t)kt * 256 * 32 + i];
            __syncthreads();
            #pragma unroll 4
            for (int k = 0; k < 256; ++k)
                acc = fmaf(row[kt * 256 + k], wsm[k * 32 + h], acc);
            __syncthreads();
        }
        acc += ilr_b[h];
        float sig = 1.f / (1.f + expf(-acc));
        int b = m >> 11, l = m & 2047;
        g_coeff[((size_t)(b * NH_ + h)) * L_ + l] =
            sig * (1.0f / (float)HD_) / (float)((l & 15) + 1);
    }
}

// ---------------------------------------------------------------------------
// mma.sync GEMM (R9 config, best measured): 128x128 tile, BK=32, 128 threads
// (4 warps, 64x64 warp tile), double-buffered cp.async, 2 CTAs/SM.
// ---------------------------------------------------------------------------
#define ROWB 80
#define MATB (128 * ROWB)          // 10240
#define STGB (4 * MATB)            // 40960
#define GEMM_SMEM (2 * STGB)       // 81920

__device__ __forceinline__ void load_stage(uint32_t sb,
    const __nv_bfloat16* __restrict__ Ah, const __nv_bfloat16* __restrict__ Al,
    const __nv_bfloat16* __restrict__ Bh, const __nv_bfloat16* __restrict__ Bl,
    int am0, int bn0, int kc, int tid)
{
    #pragma unroll
    for (int it = 0; it < 4; ++it) {
        int u = tid + it * 128;
        int row = u >> 2, ch = u & 3;
        int gcol = kc * 32 + ch * 8;
        uint32_t so = (uint32_t)(row * ROWB + ch * 16);
        size_t ga = (size_t)(am0 + row) * C_ + gcol;
        size_t gb = (size_t)(bn0 + row) * C_ + gcol;
        CP_ASYNC16(sb + so,            Ah + ga);
        CP_ASYNC16(sb + so + MATB,     Al + ga);
        CP_ASYNC16(sb + so + 2 * MATB, Bh + gb);
        CP_ASYNC16(sb + so + 3 * MATB, Bl + gb);
    }
}

template <int MODE>
__global__ __launch_bounds__(128) void gemm_mma(float* __restrict__ Cout)
{
    extern __shared__ char sm[];
    uint32_t sbase = smem_u32(sm);
    int tid = threadIdx.x, wid = tid >> 5, lane = tid & 31;
    int bn = blockIdx.x, bm = blockIdx.y;
    int wm = wid & 1, wn = wid >> 1;     // 2x2 warp grid, warp tile 64x64

    const __nv_bfloat16 *Ah, *Al, *Bh, *Bl;
    float* outP;
    if (MODE == 1) {
        int z = blockIdx.z;
        Ah = g_Ah; Al = g_Al;
        Bh = g_Wh + (size_t)z * (C_ * C_);
        Bl = g_Wl + (size_t)z * (C_ * C_);
        outP = (z == 0) ? g_XC : (z == 1) ? g_XB : g_XA;
    } else {
        Ah = g_XCWh; Al = g_XCWl;
        Bh = g_Wh + (size_t)3 * (C_ * C_);
        Bl = g_Wl + (size_t)3 * (C_ * C_);
        outP = Cout;
    }
    int am0 = bm * 128, bn0 = bn * 128;

    float acc[4][8][4];
    #pragma unroll
    for (int i = 0; i < 4; ++i)
        #pragma unroll
        for (int j = 0; j < 8; ++j)
            #pragma unroll
            for (int q = 0; q < 4; ++q) acc[i][j][q] = 0.f;

    int a_row = wm * 64 + (lane & 15);
    int a_cb  = (lane >> 4) * 16;
    int gg = lane >> 3, l8 = lane & 7;
    int b_row = wn * 64 + (gg >> 1) * 8 + l8;
    int b_cb  = (gg & 1) * 16;

    load_stage(sbase, Ah, Al, Bh, Bl, am0, bn0, 0, tid);
    CP_COMMIT();

    for (int c = 0; c < 64; ++c) {
        int st = c & 1;
        if (c + 1 < 64) {
            load_stage(sbase + (st ^ 1) * STGB, Ah, Al, Bh, Bl, am0, bn0, c + 1, tid);
            CP_COMMIT();
            CP_WAIT1();
        } else {
            CP_WAIT0();
        }
        __syncthreads();

        uint32_t S = sbase + st * STGB;
        #pragma unroll
        for (int k16 = 0; k16 < 2; ++k16) {
            uint32_t kb = (uint32_t)(k16 * 32);
            uint32_t bh[16], bl[16];
            #pragma unroll
            for (int q = 0; q < 4; ++q) {
                uint32_t ad = S + 2 * MATB + (uint32_t)((b_row + q * 16) * ROWB) + kb + b_cb;
                LDSM_X4(bh[q*4], bh[q*4+1], bh[q*4+2], bh[q*4+3], ad);
                LDSM_X4(bl[q*4], bl[q*4+1], bl[q*4+2], bl[q*4+3], ad + MATB);
            }
            #pragma unroll
            for (int mt = 0; mt < 4; ++mt) {
                uint32_t ah[4], al[4];
                uint32_t aad = S + (uint32_t)((a_row + mt * 16) * ROWB) + kb + a_cb;
                LDSM_X4(ah[0], ah[1], ah[2], ah[3], aad);
                LDSM_X4(al[0], al[1], al[2], al[3], aad + MATB);
                #pragma unroll
                for (int nt = 0; nt < 8; ++nt)
                    mma_bf16(acc[mt][nt], ah, bh[nt * 2], bh[nt * 2 + 1]);
                #pragma unroll
                for (int nt = 0; nt < 8; ++nt)
                    mma_bf16(acc[mt][nt], ah, bl[nt * 2], bl[nt * 2 + 1]);
                #pragma unroll
                for (int nt = 0; nt < 8; ++nt)
                    mma_bf16(acc[mt][nt], al, bh[nt * 2], bh[nt * 2 + 1]);
            }
        }
        __syncthreads();
    }

    #pragma unroll
    for (int mt = 0; mt < 4; ++mt) {
        #pragma unroll
        for (int nt = 0; nt < 8; ++nt) {
            int m = am0 + wm * 64 + mt * 16 + (lane >> 2);
            int n = bn0 + wn * 64 + nt * 8 + 2 * (lane & 3);
            float2 v0 = make_float2(acc[mt][nt][0], acc[mt][nt][1]);
            float2 v1 = make_float2(acc[mt][nt][2], acc[mt][nt][3]);
            if (MODE == 0) {
                *(float2*)(outP + (size_t)m * C_ + n) = v0;
                *(float2*)(outP + (size_t)(m + 8) * C_ + n) = v1;
            } else {
                int h = n >> 6, d = n & 63;
                int b = m >> 11, l = m & 2047;
                float* dst = outP + ((size_t)(b * NH_ + h) * L_ + l) * HD_ + d;
                *(float2*)dst = v0;
                *(float2*)(dst + 8 * HD_) = v1;
            }
        }
    }
}

// ---------------------------------------------------------------------------
// Scan kernel: tensor-core matmuls, cp.async input prefetch, 7 barriers/chunk.
// ---------------------------------------------------------------------------
#define SC_W1T    0                       // fp32 [64][66]
#define SC_W1TH   16896                   // bf16 [64] pitch 144
#define SC_W1TL   26112
#define SC_XBH    35328                   // bf16 [16] pitch 144
#define SC_XBL    37632
#define SC_XCH    39936
#define SC_XCL    42240
#define SC_XBT_H  44544                   // xb^T bf16 [64] pitch 48
#define SC_XBT_L  47616
#define SC_GT_H   50688                   // grad^T bf16 [64] pitch 48
#define SC_GT_L   53760
#define SC_Z1S    56832                   // fp32 [16][66]
#define SC_ACCS   61056                   // fp32 [16][66]
#define SC_GRADS  65280                   // fp32 [16][65]
#define SC_ATTN   69440                   // fp32 [16][16]
#define SC_B1     70464
#define SC_RED    70720                   // 3 slots x 64 fp32
#define SC_IN     71488                   // 2 x (3*4096 + 64) input buffers
#define SC_INSTRIDE 12352
#define SC_TOTAL  96192

// single-sync reduction; caller provides a distinct slot per call site
__device__ __forceinline__ void reduce2f(float& a, float& b, float* red, int tid)
{
    #pragma unroll
    for (int off = 16; off; off >>= 1) {
        a += __shfl_xor_sync(0xffffffffu, a, off);
        b += __shfl_xor_sync(0xffffffffu, b, off);
    }
    int warp = tid >> 5;
    if ((tid & 31) == 0) { red[warp * 2] = a; red[warp * 2 + 1] = b; }
    __syncthreads();
    int rr = tid >> 6;
    a = red[rr * 4 + 0] + red[rr * 4 + 2];
    b = red[rr * 4 + 1] + red[rr * 4 + 3];
}

__device__ __forceinline__ void scan_prefetch(uint32_t sbin,
    const float* XBp, const float* XCp, const float* XAp, const float* cop,
    int c, int tid)
{
    if (tid < 772) {
        int which = tid >> 8;
        if (which < 3) {
            int t = tid & 255;
            const float* src = (which == 0) ? XBp : (which == 1) ? XCp : XAp;
            CP_ASYNC16(sbin + which * 4096 + t * 16, src + (size_t)c * 1024 + t * 4);
        } else {
            int t = tid - 768;              // 0..3
            CP_ASYNC16(sbin + 12288 + t * 16, cop + c * 16 + t * 4);
        }
    }
}

__global__ __launch_bounds__(1024) void scan_kernel(const float* __restrict__ W1g,
                                                    const float* __restrict__ b1g,
                                                    const float* __restrict__ lnwg,
                                                    const float* __restrict__ lnbg)
{
    extern __shared__ char sm[];
    uint32_t sbase = smem_u32(sm);
    float* W1Tp  = (float*)(sm + SC_W1T);
    float* z1s   = (float*)(sm + SC_Z1S);
    float* accs  = (float*)(sm + SC_ACCS);
    float* grads = (float*)(sm + SC_GRADS);
    float* attn  = (float*)(sm + SC_ATTN);
    float* b1s   = (float*)(sm + SC_B1);
    float* red   = (float*)(sm + SC_RED);

    int bh = blockIdx.x;
    int h = bh & 31;
    int b = bh >> 5;
    int tid = threadIdx.x;
    int wid = tid >> 5, lane = tid & 31;
    int r = tid >> 6;
    int d = tid & 63;

    for (int i = tid; i < 4096; i += 1024) {
        int dd = i & 63, kk = i >> 6;
        float v = W1g[(size_t)h * 4096 + kk * 64 + dd];
        W1Tp[dd * 66 + kk] = v;
        __nv_bfloat16 hv = __float2bfloat16(v);
        *(__nv_bfloat16*)(sm + SC_W1TH + dd * 144 + kk * 2) = hv;
        *(__nv_bfloat16*)(sm + SC_W1TL + dd * 144 + kk * 2) =
            __float2bfloat16(v - __bfloat162float(hv));
    }
    if (tid < 64) b1s[tid] = b1g[(size_t)h * 64 + tid];
    float lnw = lnwg[(size_t)h * 64 + d];
    float lnb = lnbg[(size_t)h * 64 + d];

    const float* XCp = g_XC + (size_t)bh * (L_ * HD_);
    const float* XBp = g_XB + (size_t)bh * (L_ * HD_);
    const float* XAp = g_XA + (size_t)bh * (L_ * HD_);
    const float* cop = g_coeff + (size_t)bh * L_;

    // prefetch chunk 0
    scan_prefetch(sbase + SC_IN, XBp, XCp, XAp, cop, 0, tid);
    CP_COMMIT();
    CP_WAIT0();
    __syncthreads();

    for (int c = 0; c < NC_; ++c) {
        int cur = c & 1;
        float* inb = (float*)(sm + SC_IN + cur * SC_INSTRIDE);
        // ---- p1: read inputs from smem, build bf16 tiles, start next prefetch
        float xb_e = inb[tid];
        float xc_e = inb[1024 + tid];
        float xa_e = inb[2048 + tid];
        const float* cosp = inb + 3072;
        {
            __nv_bfloat16 bh16 = __float2bfloat16(xb_e);
            __nv_bfloat16 bl16 = __float2bfloat16(xb_e - __bfloat162float(bh16));
            *(__nv_bfloat16*)(sm + SC_XBH + r * 144 + d * 2) = bh16;
            *(__nv_bfloat16*)(sm + SC_XBL + r * 144 + d * 2) = bl16;
            *(__nv_bfloat16*)(sm + SC_XBT_H + d * 48 + r * 2) = bh16;
            *(__nv_bfloat16*)(sm + SC_XBT_L + d * 48 + r * 2) = bl16;
            __nv_bfloat16 ch16 = __float2bfloat16(xc_e);
            *(__nv_bfloat16*)(sm + SC_XCH + r * 144 + d * 2) = ch16;
            *(__nv_bfloat16*)(sm + SC_XCL + r * 144 + d * 2) =
                __float2bfloat16(xc_e - __bfloat162float(ch16));
        }
        if (c + 1 < NC_) {
            scan_prefetch(sbase + SC_IN + (cur ^ 1) * SC_INSTRIDE,
                          XBp, XCp, XAp, cop, c + 1, tid);
            CP_COMMIT();
        }
        __syncthreads();

        // ---- p2: MMA z1 (warps 0-3), xc@W1 (warps 4-7), attn (warp 8)
        if (wid < 8) {
            int isAcc = wid >> 2;
            int w = wid & 3;
            uint32_t AhB = sbase + (isAcc ? SC_XCH : SC_XBH);
            uint32_t AlB = sbase + (isAcc ? SC_XCL : SC_XBL);
            int n0 = w * 16;
            float c0[4] = {0,0,0,0}, c1[4] = {0,0,0,0};
            uint32_t a_off = (uint32_t)((lane & 15) * 144 + (lane >> 4) * 16);
            int g = lane >> 3;
            uint32_t b_off = (uint32_t)((n0 + ((g >> 1) << 3) + (lane & 7)) * 144 + (g & 1) * 16);
            #pragma unroll
            for (int ks = 0; ks < 4; ++ks) {
                uint32_t ah[4], al[4], bhf[4], blf[4];
                LDSM_X4(ah[0], ah[1], ah[2], ah[3], AhB + a_off + ks * 32);
                LDSM_X4(al[0], al[1], al[2], al[3], AlB + a_off + ks * 32);
                LDSM_X4(bhf[0], bhf[1], bhf[2], bhf[3], sbase + SC_W1TH + b_off + ks * 32);
                LDSM_X4(blf[0], blf[1], blf[2], blf[3], sbase + SC_W1TL + b_off + ks * 32);
                mma_bf16(c0, ah, bhf[0], bhf[1]); mma_bf16(c1, ah, bhf[2], bhf[3]);
                mma_bf16(c0, ah, blf[0], blf[1]); mma_bf16(c1, ah, blf[2], blf[3]);
                mma_bf16(c0, al, bhf[0], bhf[1]); mma_bf16(c1, al, bhf[2], bhf[3]);
            }
            float* outb = isAcc ? accs : z1s;
            int row = lane >> 2, col0 = n0 + 2 * (lane & 3);
            *(float2*)&outb[row * 66 + col0]           = make_float2(c0[0], c0[1]);
            *(float2*)&outb[(row + 8) * 66 + col0]     = make_float2(c0[2], c0[3]);
            *(float2*)&outb[row * 66 + col0 + 8]       = make_float2(c1[0], c1[1]);
            *(float2*)&outb[(row + 8) * 66 + col0 + 8] = make_float2(c1[2], c1[3]);
        } else if (wid == 8) {
            float c0[4] = {0,0,0,0}, c1[4] = {0,0,0,0};
            uint32_t a_off = (uint32_t)((lane & 15) * 144 + (lane >> 4) * 16);
            int g = lane >> 3;
            uint32_t b_off = (uint32_t)((((g >> 1) << 3) + (lane & 7)) * 144 + (g & 1) * 16);
            #pragma unroll
            for (int ks = 0; ks < 4; ++ks) {
                uint32_t ah[4], al[4], bhf[4], blf[4];
                LDSM_X4(ah[0], ah[1], ah[2], ah[3], sbase + SC_XCH + a_off + ks * 32);
                LDSM_X4(al[0], al[1], al[2], al[3], sbase + SC_XCL + a_off + ks * 32);
                LDSM_X4(bhf[0], bhf[1], bhf[2], bhf[3], sbase + SC_XBH + b_off + ks * 32);
                LDSM_X4(blf[0], blf[1], blf[2], blf[3], sbase + SC_XBL + b_off + ks * 32);
                mma_bf16(c0, ah, bhf[0], bhf[1]); mma_bf16(c1, ah, bhf[2], bhf[3]);
                mma_bf16(c0, ah, blf[0], blf[1]); mma_bf16(c1, ah, blf[2], blf[3]);
                mma_bf16(c0, al, bhf[0], bhf[1]); mma_bf16(c1, al, bhf[2], bhf[3]);
            }
            int row = lane >> 2, col0 = 2 * (lane & 3);
            *(float2*)&attn[row * 16 + col0]           = make_float2(c0[0], c0[1]);
            *(float2*)&attn[(row + 8) * 16 + col0]     = make_float2(c0[2], c0[3]);
            *(float2*)&attn[row * 16 + col0 + 8]       = make_float2(c1[0], c1[1]);
            *(float2*)&attn[(row + 8) * 16 + col0 + 8] = make_float2(c1[2], c1[3]);
        }
        __syncthreads();

        // ---- p3: LN-bwd grad
        float z1 = z1s[r * 66 + d] + b1s[d];
        float s1 = z1, s2 = z1 * z1;
        reduce2f(s1, s2, red, tid);
        float mu = s1 * (1.f / 64.f);
        float var = s2 * (1.f / 64.f) - mu * mu;
        float rstd = rsqrtf(var + EPS_);
        float xhat = (z1 - mu) * rstd;
        float y = fmaf(lnw, xhat, lnb);
        float g = (y - (xa_e - xb_e)) * lnw;
        float sg = g, sgx = g * xhat;
        reduce2f(sg, sgx, red + 64, tid);
        float grad = (64.f * g - sg - xhat * sgx) * (rstd * (1.f / 64.f));
        grads[r * 65 + d] = grad;
        {
            __nv_bfloat16 gh = __float2bfloat16(grad);
            *(__nv_bfloat16*)(sm + SC_GT_H + d * 48 + r * 2) = gh;
            *(__nv_bfloat16*)(sm + SC_GT_L + d * 48 + r * 2) =
                __float2bfloat16(grad - __bfloat162float(gh));
        }
        __syncthreads();

        // ---- p4 (warps 8-15 ONLY, overlapped with p5 on other warps):
        // W1 -= c15 * grad^T @ xb, with fused bf16 hi/lo rewrite
        if (wid >= 8 && wid < 16) {
            int wq = wid - 8;
            int m0 = (wq >> 1) * 16;
            int nb = (wq & 1) * 32;
            uint32_t a_off = (uint32_t)((m0 + (lane & 15)) * 48 + (lane >> 4) * 16);
            uint32_t ah[4], al[4];
            LDSM_X4(ah[0], ah[1], ah[2], ah[3], sbase + SC_GT_H + a_off);
            LDSM_X4(al[0], al[1], al[2], al[3], sbase + SC_GT_L + a_off);
            int g2 = lane >> 3;
            float cc[4][4];
            #pragma unroll
            for (int i = 0; i < 4; ++i)
                #pragma unroll
                for (int q = 0; q < 4; ++q) cc[i][q] = 0.f;
            #pragma unroll
            for (int half = 0; half < 2; ++half) {
                int n0 = nb + half * 16;
                uint32_t b_off = (uint32_t)((n0 + ((g2 >> 1) << 3) + (lane & 7)) * 48 + (g2 & 1) * 16);
                uint32_t bhf[4], blf[4];
                LDSM_X4(bhf[0], bhf[1], bhf[2], bhf[3], sbase + SC_XBT_H + b_off);
                LDSM_X4(blf[0], blf[1], blf[2], blf[3], sbase + SC_XBT_L + b_off);
                mma_bf16(cc[half*2],   ah, bhf[0], bhf[1]);
                mma_bf16(cc[half*2+1], ah, bhf[2], bhf[3]);
                mma_bf16(cc[half*2],   ah, blf[0], blf[1]);
                mma_bf16(cc[half*2+1], ah, blf[2], blf[3]);
                mma_bf16(cc[half*2],   al, bhf[0], bhf[1]);
                mma_bf16(cc[half*2+1], al, bhf[2], bhf[3]);
            }
            float c15 = cosp[15];
            int row = m0 + (lane >> 2), colb = 2 * (lane & 3);
            #pragma unroll
            for (int nt = 0; nt < 4; ++nt) {
                int col = nb + nt * 8 + colb;
                float2 v = *(float2*)&W1Tp[row * 66 + col];
                v.x -= c15 * cc[nt][0]; v.y -= c15 * cc[nt][1];
                *(float2*)&W1Tp[row * 66 + col] = v;
                {
                    __nv_bfloat16 h0 = __float2bfloat16(v.x), h1 = __float2bfloat16(v.y);
                    *(__nv_bfloat162*)(sm + SC_W1TH + row * 144 + col * 2) =
                        __halves2bfloat162(h0, h1);
                    *(__nv_bfloat162*)(sm + SC_W1TL + row * 144 + col * 2) =
                        __halves2bfloat162(
                            __float2bfloat16(v.x - __bfloat162float(h0)),
                            __float2bfloat16(v.y - __bfloat162float(h1)));
                }
                float2 w2 = *(float2*)&W1Tp[(row + 8) * 66 + col];
                w2.x -= c15 * cc[nt][2]; w2.y -= c15 * cc[nt][3];
                *(float2*)&W1Tp[(row + 8) * 66 + col] = w2;
                {
                    __nv_bfloat16 h0 = __float2bfloat16(w2.x), h1 = __float2bfloat16(w2.y);
                    *(__nv_bfloat162*)(sm + SC_W1TH + (row + 8) * 144 + col * 2) =
                        __halves2bfloat162(h0, h1);
                    *(__nv_bfloat162*)(sm + SC_W1TL + (row + 8) * 144 + col * 2) =
                        __halves2bfloat162(
                            __float2bfloat16(w2.x - __bfloat162float(h0)),
                            __float2bfloat16(w2.y - __bfloat162float(h1)));
                }
            }
        }

        // ---- p5 (all warps): Z1_bar, LN-fwd, output
        float acc = accs[r * 66 + d] + b1s[d];
        float s_attn = 0.f, s_cum = 0.f;
        #pragma unroll
        for (int j = 0; j < 16; ++j) {
            float gj = grads[j * 65 + d];
            if (j <= r) {
                s_cum += gj;
                s_attn = fmaf(attn[r * 16 + j], gj, s_attn);
            }
        }
        float co = cosp[r];
        float z1b = acc - co * (s_attn + s_cum);
        float b1new = 0.f;
        if (r == 15) b1new = b1s[d] - co * s_cum;

        float t1 = z1b, t2 = z1b * z1b;
        reduce2f(t1, t2, red + 128, tid);
        float mu2 = t1 * (1.f / 64.f);
        float rstd2 = rsqrtf(t2 * (1.f / 64.f) - mu2 * mu2 + EPS_);
        float outv = xc_e + fmaf(lnw, (z1b - mu2) * rstd2, lnb);
        int l = c * 16 + r;
        size_t oidx = ((size_t)(b * L_ + l)) * C_ + h * 64 + d;
        __nv_bfloat16 hv = __float2bfloat16(outv);
        g_XCWh[oidx] = hv;
        g_XCWl[oidx] = __float2bfloat16(outv - __bfloat162float(hv));

        CP_WAIT0();
        __syncthreads();
        if (r == 15) b1s[d] = b1new;
    }
}

// ---------------------------------------------------------------------------
extern "C" void kernel_launch(void* const* d_in, const int* in_sizes, int n_in,
                              void* d_out, int out_size)
{
    const float* hs    = (const float*)d_in[0];
    const float* Wq    = (const float*)d_in[1];
    const float* Wk    = (const float*)d_in[2];
    const float* Wv    = (const float*)d_in[3];
    const float* Wo    = (const float*)d_in[4];
    const float* ilr_w = (const float*)d_in[5];
    const float* ilr_b = (const float*)d_in[6];
    const float* lnw   = (const float*)d_in[7];
    const float* lnb   = (const float*)d_in[8];
    const float* W1    = (const float*)d_in[9];
    const float* b1    = (const float*)d_in[10];
    float* out = (float*)d_out;

    cudaFuncSetAttribute(gemm_mma<1>, cudaFuncAttributeMaxDynamicSharedMemorySize, GEMM_SMEM);
    cudaFuncSetAttribute(gemm_mma<0>, cudaFuncAttributeMaxDynamicSharedMemorySize, GEMM_SMEM);
    cudaFuncSetAttribute(scan_kernel, cudaFuncAttributeMaxDynamicSharedMemorySize, SC_TOTAL);

    prep_kernel<<<NCONV + NWT + NILR, 256, PREP_SMEM>>>(hs, Wq, Wk, Wv, Wo, ilr_w, ilr_b);

    gemm_mma<1><<<dim3(C_ / 128, M_ / 128, 3), 128, GEMM_SMEM>>>(nullptr);

    scan_kernel<<<B_ * NH_, 1024, SC_TOTAL>>>(W1, b1, lnw, lnb);

    gemm_mma<0><<<dim3(C_ / 128, M_ / 128, 1), 128, GEMM_SMEM>>>(out);
}